// round 1
// baseline (speedup 1.0000x reference)
#include <cuda_runtime.h>
#include <math.h>

// ---------------- problem constants ----------------
#define BQ   4096
#define DD   2048
#define HH   16
#define HDD  128
#define NBB  16
#define BDD  8
#define PROJ 2730          // int(4/3 * 2048)
#define UPN  (2*PROJ)      // 5460
#define N_ELE (BQ*DD)      // 8,388,608
#define GATED_LD 2736      // ceil8(2730), keeps float4 A-loads aligned

// ---------------- scratch (static device globals; no allocation) ----------------
__device__ float g_xt[N_ELE];          // x_t, later reused as GroupNorm output
__device__ float g_gates[4L*N_ELE];    // gate preacts [i,f,z,o]; later reused for `up` (BQ*5460 fits)
__device__ float g_ht[N_ELE];          // h_t for GroupNorm
__device__ float g_gated[(size_t)BQ*GATED_LD];  // GLU output, K-padded with zeros

// ---------------- LayerNorm (eps = 2048, replicating the flax quirk) ----------------
__global__ void ln_kernel(const float* __restrict__ seq,
                          const float* __restrict__ sc,
                          const float* __restrict__ bi)
{
    int b = blockIdx.x, t = threadIdx.x;
    const float* row = seq + ((size_t)b << 11);
    float v[8]; float s = 0.f, sq = 0.f;
#pragma unroll
    for (int q = 0; q < 8; q++) {
        v[q] = row[q*256 + t];
        s += v[q];
        sq = fmaf(v[q], v[q], sq);
    }
    __shared__ float sh_s[8], sh_q[8];
    __shared__ float s_mu, s_inv;
#pragma unroll
    for (int o = 16; o; o >>= 1) {
        s  += __shfl_down_sync(0xffffffffu, s,  o);
        sq += __shfl_down_sync(0xffffffffu, sq, o);
    }
    int warp = t >> 5, lane = t & 31;
    if (lane == 0) { sh_s[warp] = s; sh_q[warp] = sq; }
    __syncthreads();
    if (t == 0) {
        float ts = 0.f, tq = 0.f;
        for (int w = 0; w < 8; w++) { ts += sh_s[w]; tq += sh_q[w]; }
        float mu  = ts / 2048.f;
        float var = tq / 2048.f - mu*mu;
        s_mu  = mu;
        s_inv = rsqrtf(var + 2048.0f);   // EPS_LN = inp_dim = 2048
    }
    __syncthreads();
    float mu = s_mu, inv = s_inv;
#pragma unroll
    for (int q = 0; q < 8; q++) {
        int col = q*256 + t;
        g_xt[((size_t)b << 11) + col] = (v[q] - mu) * inv * sc[col] + bi[col];
    }
}

// ---------------- generic fp32 SGEMM: C[M,N] = A[M,K](lda) * B[K,N] (+bias +resid) ----------------
#define BM 128
#define BN 128
#define BK 8
__global__ __launch_bounds__(256, 2)
void sgemm_k(const float* __restrict__ A, int lda,
             const float* __restrict__ B,
             float* __restrict__ C,
             int M, int N, int K,
             const float* __restrict__ bias,
             const float* __restrict__ resid)
{
    __shared__ float As[BK][BM];
    __shared__ float Bs[BK][BN];
    int tid = threadIdx.x;
    int n0 = blockIdx.x * BN;
    int m0 = blockIdx.y * BM;
    int tx = tid & 15, ty = tid >> 4;

    float acc[8][8];
#pragma unroll
    for (int i = 0; i < 8; i++)
#pragma unroll
        for (int j = 0; j < 8; j++) acc[i][j] = 0.f;

    int ar  = tid >> 1;            // A tile row 0..127
    int akc = (tid & 1) << 2;      // A tile k-col {0,4}
    int bkr = tid >> 5;            // B tile k-row 0..7
    int bc  = (tid & 31) << 2;     // B tile col 0..124 step4

    const float* Aptr = A + (size_t)(m0 + ar) * lda + akc;

    for (int k0 = 0; k0 < K; k0 += BK) {
        // register-stage the loads (lda is padded to >= ceil8(K), so A k-range is always valid)
        float4 va = make_float4(0.f, 0.f, 0.f, 0.f);
        if (m0 + ar < M) va = *(const float4*)(Aptr + k0);
        float4 vb = make_float4(0.f, 0.f, 0.f, 0.f);
        if (k0 + bkr < K && n0 + bc < N)
            vb = *(const float4*)(B + (size_t)(k0 + bkr) * N + n0 + bc);

        __syncthreads();
        As[akc+0][ar] = va.x; As[akc+1][ar] = va.y;
        As[akc+2][ar] = va.z; As[akc+3][ar] = va.w;
        Bs[bkr][bc+0] = vb.x; Bs[bkr][bc+1] = vb.y;
        Bs[bkr][bc+2] = vb.z; Bs[bkr][bc+3] = vb.w;
        __syncthreads();

#pragma unroll
        for (int kc = 0; kc < BK; kc++) {
            float a[8], bb[8];
#pragma unroll
            for (int i = 0; i < 8; i++) a[i]  = As[kc][ty*8 + i];
#pragma unroll
            for (int j = 0; j < 8; j++) bb[j] = Bs[kc][tx*8 + j];
#pragma unroll
            for (int i = 0; i < 8; i++)
#pragma unroll
                for (int j = 0; j < 8; j++)
                    acc[i][j] = fmaf(a[i], bb[j], acc[i][j]);
        }
    }

#pragma unroll
    for (int i = 0; i < 8; i++) {
        int row = m0 + ty*8 + i;
        if (row >= M) continue;
        size_t roff = (size_t)row * N;
#pragma unroll
        for (int j = 0; j < 8; j++) {
            int col = n0 + tx*8 + j;
            if (col >= N) continue;
            float v = acc[i][j];
            if (bias)  v += bias[col];
            if (resid) v += resid[roff + col];
            C[roff + col] = v;
        }
    }
}

// ---------------- gating + block-diag recurrence + state outputs ----------------
__global__ void gate_kernel(
    const float* __restrict__ b_i, const float* __restrict__ b_f,
    const float* __restrict__ b_z, const float* __restrict__ b_o,
    const float* __restrict__ Riw, const float* __restrict__ Rib,
    const float* __restrict__ Rfw, const float* __restrict__ Rfb,
    const float* __restrict__ Rzw, const float* __restrict__ Rzb,
    const float* __restrict__ Row_, const float* __restrict__ Rob,
    const float* __restrict__ c_tm1, const float* __restrict__ n_tm1,
    const float* __restrict__ h_tm1, const float* __restrict__ m_tm1,
    float* __restrict__ out, int write_states)
{
    size_t idx = (size_t)blockIdx.x * blockDim.x + threadIdx.x;
    if (idx >= (size_t)N_ELE) return;
    int b = (int)(idx >> 11);
    int j = (int)(idx & 2047);
    int h = j >> 7;
    int rem = j & 127;
    int n = rem >> 3;
    int e = rem & 7;

    // block-diagonal recurrence term:  sum_d h[b,h,n,d] * R[n,d,e] + Rb[n,e]
    const float* hp = h_tm1 + ((size_t)b << 11) + (h << 7) + (n << 3);
    float hv[8];
#pragma unroll
    for (int d = 0; d < 8; d++) hv[d] = hp[d];
    int sb = n*8 + e;
    int wb = n*64 + e;
    float bi_ = Rib[sb], bf_ = Rfb[sb], bz_ = Rzb[sb], bo_ = Rob[sb];
#pragma unroll
    for (int d = 0; d < 8; d++) {
        float hd = hv[d];
        bi_ = fmaf(hd, Riw[wb + d*8], bi_);
        bf_ = fmaf(hd, Rfw[wb + d*8], bf_);
        bz_ = fmaf(hd, Rzw[wb + d*8], bz_);
        bo_ = fmaf(hd, Row_[wb + d*8], bo_);
    }

    float it = g_gates[idx]              + b_i[j] + bi_;
    float ft = g_gates[(size_t)N_ELE   + idx] + b_f[j] + bf_;
    float zt = g_gates[(size_t)2*N_ELE + idx] + b_z[j] + bz_;
    float ot = g_gates[(size_t)3*N_ELE + idx] + b_o[j] + bo_;

    float mprev = m_tm1[idx];
    float mt = fmaxf(ft + mprev, it);
    float ie = expf(it - mt);
    float fe = expf(ft - mt + mprev);
    float z  = tanhf(zt);
    float ct = fe * c_tm1[idx] + ie * z;
    float nt = fe * n_tm1[idx] + ie;
    float o  = 1.f / (1.f + expf(-ot));
    float ht = o * (ct / nt);

    g_ht[idx] = ht;
    if (write_states) {
        out[(size_t)N_ELE   + idx] = ct;
        out[(size_t)2*N_ELE + idx] = nt;
        out[(size_t)3*N_ELE + idx] = ht;
        out[(size_t)4*N_ELE + idx] = mt;
    }
}

// ---------------- GroupNorm (G=16 groups over (head, dg) axes), eps=1e-6 ----------------
__global__ void gn_kernel(const float* __restrict__ sc, const float* __restrict__ bi)
{
    int b = blockIdx.x, t = threadIdx.x;
    __shared__ float row[2048];
    __shared__ float ps[256], pq[256];
    __shared__ float gmu[16], gis[16];
    const float* hr = g_ht + ((size_t)b << 11);
#pragma unroll
    for (int q = 0; q < 8; q++) row[q*256 + t] = hr[q*256 + t];
    __syncthreads();

    int g = t >> 4, p = t & 15;    // p indexes the head axis
    float s = 0.f, sq = 0.f;
#pragma unroll
    for (int dg = 0; dg < 8; dg++) {
        float v = row[p*128 + g*8 + dg];
        s += v; sq = fmaf(v, v, sq);
    }
    ps[t] = s; pq[t] = sq;
    __syncthreads();
    for (int st = 8; st > 0; st >>= 1) {
        if (p < st) { ps[t] += ps[t + st]; pq[t] += pq[t + st]; }
        __syncthreads();
    }
    if (p == 0) {
        float mu  = ps[t] / 128.f;
        float var = pq[t] / 128.f - mu*mu;
        gmu[g] = mu;
        gis[g] = rsqrtf(var + 1e-6f);
    }
    __syncthreads();
#pragma unroll
    for (int q = 0; q < 8; q++) {
        int col = q*256 + t;
        int hd  = col & 127;
        int gg  = hd >> 3;
        float v = (row[col] - gmu[gg]) * gis[gg];
        g_xt[((size_t)b << 11) + col] = v * sc[hd] + bi[hd];   // reuse g_xt
    }
}

// ---------------- GLU: gated = up[:, :PROJ] + gelu_tanh(up[:, PROJ:]) ----------------
__global__ void glu_kernel()
{
    size_t idx = (size_t)blockIdx.x * blockDim.x + threadIdx.x;
    if (idx >= (size_t)BQ * GATED_LD) return;
    int b = (int)(idx / GATED_LD);
    int j = (int)(idx - (size_t)b * GATED_LD);
    float r = 0.f;                      // zero K-padding columns
    if (j < PROJ) {
        const float* up = g_gates + (size_t)b * UPN;
        float a = up[j];
        float x = up[j + PROJ];
        float x3 = x * x * x;
        float gg = 0.5f * x * (1.f + tanhf(0.7978845608028654f * (x + 0.044715f * x3)));
        r = a + gg;
    }
    g_gated[(size_t)b * GATED_LD + j] = r;
}

// ---------------- driver ----------------
extern "C" void kernel_launch(void* const* d_in, const int* in_sizes, int n_in,
                              void* d_out, int out_size)
{
    const float* seq      = (const float*)d_in[0];
    const float* c_tm1    = (const float*)d_in[1];
    const float* n_tm1    = (const float*)d_in[2];
    const float* h_tm1    = (const float*)d_in[3];
    const float* m_tm1    = (const float*)d_in[4];
    const float* ln_scale = (const float*)d_in[5];
    const float* ln_bias  = (const float*)d_in[6];
    const float* W_z      = (const float*)d_in[7];
    const float* b_z      = (const float*)d_in[8];
    const float* W_i      = (const float*)d_in[9];
    const float* b_i      = (const float*)d_in[10];
    const float* W_f      = (const float*)d_in[11];
    const float* b_f      = (const float*)d_in[12];
    const float* W_o      = (const float*)d_in[13];
    const float* b_o      = (const float*)d_in[14];
    const float* R_z_w    = (const float*)d_in[15];
    const float* R_z_b    = (const float*)d_in[16];
    const float* R_i_w    = (const float*)d_in[17];
    const float* R_i_b    = (const float*)d_in[18];
    const float* R_f_w    = (const float*)d_in[19];
    const float* R_f_b    = (const float*)d_in[20];
    const float* R_o_w    = (const float*)d_in[21];
    const float* R_o_b    = (const float*)d_in[22];
    const float* gn_scale = (const float*)d_in[23];
    const float* gn_bias  = (const float*)d_in[24];
    const float* up_w     = (const float*)d_in[25];
    const float* up_b     = (const float*)d_in[26];
    const float* down_w   = (const float*)d_in[27];
    const float* down_b   = (const float*)d_in[28];
    float* out = (float*)d_out;

    int write_states = (out_size >= 5 * N_ELE) ? 1 : 0;

    void *p_xt, *p_gates, *p_gated;
    cudaGetSymbolAddress(&p_xt,    g_xt);
    cudaGetSymbolAddress(&p_gates, g_gates);
    cudaGetSymbolAddress(&p_gated, g_gated);
    float* xt    = (float*)p_xt;
    float* gates = (float*)p_gates;
    float* gated = (float*)p_gated;

    // 1. LayerNorm
    ln_kernel<<<BQ, 256>>>(seq, ln_scale, ln_bias);

    // 2. Four gate GEMMs: x_t @ W_{i,f,z,o} -> g_gates slots [i,f,z,o]
    dim3 gg(DD / BN, BQ / BM);
    sgemm_k<<<gg, 256>>>(xt, DD, W_i, gates + 0L*N_ELE, BQ, DD, DD, nullptr, nullptr);
    sgemm_k<<<gg, 256>>>(xt, DD, W_f, gates + 1L*N_ELE, BQ, DD, DD, nullptr, nullptr);
    sgemm_k<<<gg, 256>>>(xt, DD, W_z, gates + 2L*N_ELE, BQ, DD, DD, nullptr, nullptr);
    sgemm_k<<<gg, 256>>>(xt, DD, W_o, gates + 3L*N_ELE, BQ, DD, DD, nullptr, nullptr);

    // 3. gating + recurrence + states
    gate_kernel<<<N_ELE / 256, 256>>>(b_i, b_f, b_z, b_o,
                                      R_i_w, R_i_b, R_f_w, R_f_b,
                                      R_z_w, R_z_b, R_o_w, R_o_b,
                                      c_tm1, n_tm1, h_tm1, m_tm1,
                                      out, write_states);

    // 4. GroupNorm -> g_xt (reused)
    gn_kernel<<<BQ, 256>>>(gn_scale, gn_bias);

    // 5. up GEMM: gn_out @ up_w + up_b -> g_gates (reused, BQ x 5460)
    sgemm_k<<<dim3((UPN + BN - 1) / BN, BQ / BM), 256>>>(
        xt, DD, up_w, gates, BQ, UPN, DD, up_b, nullptr);

    // 6. GLU gate
    glu_kernel<<<(int)(((size_t)BQ * GATED_LD) / 256), 256>>>();

    // 7. down GEMM + bias + residual(seq) -> out
    sgemm_k<<<dim3(DD / BN, BQ / BM), 256>>>(
        gated, GATED_LD, down_w, out, BQ, DD, PROJ, down_b, seq);
}

// round 3
// speedup vs baseline: 2.2013x; 2.2013x over previous
#include <cuda_runtime.h>
#include <cuda_bf16.h>
#include <cstdint>
#include <math.h>

// ================= problem constants =================
#define BQ   4096
#define DD   2048
#define PROJ 2730
#define UPN  5460
#define N_ELE (BQ*DD)

// split-bf16 K layouts: K' = 3*Kpad, segments [A_hi | A_lo | A_hi] x [B_hi | B_hi | B_lo]
#define KP1   2048            // gates / up
#define LDA1  (3*KP1)         // 6144
#define KP2   2752            // down (2730 padded to mult of 64)
#define LDA2  (3*KP2)         // 8256
#define NPAD_UP 5632          // 44 * 128

// ================= scratch (static device globals) =================
__device__ __align__(256) __nv_bfloat16 gA [(size_t)BQ*LDA2];        // activation split (max layout)
__device__ __align__(256) __nv_bfloat16 gBg[(size_t)4*DD*LDA1];      // W_i,f,z,o transposed+split
__device__ __align__(256) __nv_bfloat16 gBu[(size_t)NPAD_UP*LDA1];   // up_w
__device__ __align__(256) __nv_bfloat16 gBd[(size_t)DD*LDA2];        // down_w
__device__ __align__(16) float g_xt[N_ELE];
__device__ __align__(16) float g_gates[(size_t)4*N_ELE];             // gate preacts; reused for `up`
__device__ __align__(16) float g_ht[N_ELE];
__device__ __align__(16) float g_gated[(size_t)BQ*PROJ];

// ================= PTX helpers =================
__device__ __forceinline__ uint32_t smem_u32(const void* p){
    uint32_t a; asm("{ .reg .u64 t; cvta.to.shared.u64 t, %1; cvt.u32.u64 %0, t; }" : "=r"(a) : "l"(p));
    return a;
}
#define CP16(s, g) asm volatile("cp.async.cg.shared.global [%0], [%1], 16;" :: "r"(s), "l"(g) : "memory")
#define CP_COMMIT() asm volatile("cp.async.commit_group;" ::: "memory")

#define LDSM_X4(r0,r1,r2,r3,addr) \
    asm volatile("ldmatrix.sync.aligned.m8n8.x4.shared.b16 {%0,%1,%2,%3}, [%4];" \
        : "=r"(r0), "=r"(r1), "=r"(r2), "=r"(r3) : "r"(addr))
#define LDSM_X2(r0,r1,addr) \
    asm volatile("ldmatrix.sync.aligned.m8n8.x2.shared.b16 {%0,%1}, [%2];" \
        : "=r"(r0), "=r"(r1) : "r"(addr))
#define MMA16816(d, a0,a1,a2,a3, b0,b1) \
    asm volatile("mma.sync.aligned.m16n8k16.row.col.f32.bf16.bf16.f32 " \
        "{%0,%1,%2,%3}, {%4,%5,%6,%7}, {%8,%9}, {%0,%1,%2,%3};" \
        : "+f"((d)[0]), "+f"((d)[1]), "+f"((d)[2]), "+f"((d)[3]) \
        : "r"(a0), "r"(a1), "r"(a2), "r"(a3), "r"(b0), "r"(b1))

// granule swizzle for BK=32 bf16 tiles (rows of 4 x 16B granules):
// g(r,c) = r*4 + (c ^ ((r>>1)&3)); conflict-free for ldmatrix 8-row phases
__device__ __forceinline__ uint32_t swz(int r, int c){
    return (uint32_t)((r*4 + (c ^ ((r>>1)&3))) * 16);
}

// ================= HMMA GEMM: C[M,N] = A[M,K'] * Bt[N,K']^T =================
// A [M,K'] bf16 row-major (lda elems); Bt [Npad,K'] bf16 row-major (ldb elems)
#define BM 128
#define BN 128
#define BK 32

__global__ void __launch_bounds__(256) mma_gemm(
    const __nv_bfloat16* __restrict__ A, long lda,
    const __nv_bfloat16* __restrict__ B, long ldb,
    float* __restrict__ C, int N, int ldc, int Kp,
    long bStride, long cStride,
    const float* __restrict__ bias,
    const float* __restrict__ resid)
{
    __shared__ __align__(1024) char smem[4*8192];   // A0,B0,A1,B1
    uint32_t base = smem_u32(smem);

    int tid  = threadIdx.x;
    int lane = tid & 31;
    int wid  = tid >> 5;
    int n0 = blockIdx.x * BN;
    int m0 = blockIdx.y * BM;
    B += (long)blockIdx.z * bStride;
    C += (long)blockIdx.z * cStride;

    // ---- loader slots: each thread owns 2 consecutive 16B granules of one row
    int lr = tid >> 1;           // row 0..127
    int lc = (tid & 1) * 2;      // granule 0 or 2
    const char* gAp = (const char*)(A + (long)(m0 + lr) * lda) + lc*16;
    const char* gBp = (const char*)(B + (long)(n0 + lr) * ldb) + lc*16;
    uint32_t so0 = swz(lr, lc);
    uint32_t so1 = swz(lr, lc + 1);

    // ---- warp tiling: 2 (m) x 4 (n) warps; warp tile 64m x 32n
    int warp_m = wid & 1;
    int warp_n = wid >> 1;

    // fragment row bases
    int rA[4], rB[4];
#pragma unroll
    for (int mt = 0; mt < 4; mt++) rA[mt] = warp_m*64 + mt*16 + (lane & 15);
#pragma unroll
    for (int nt = 0; nt < 4; nt++) rB[nt] = warp_n*32 + nt*8 + (lane & 7);
    int cAoff = lane >> 4;          // 0/1
    int cBoff = (lane >> 3) & 1;    // 0/1

    float acc[4][4][4];
#pragma unroll
    for (int mt = 0; mt < 4; mt++)
#pragma unroll
        for (int nt = 0; nt < 4; nt++)
#pragma unroll
            for (int q = 0; q < 4; q++) acc[mt][nt][q] = 0.f;

    int NC = Kp / BK;

    // prologue: chunk 0 -> buf 0
    {
        CP16(base + so0,        gAp);
        CP16(base + so1,        gAp + 16);
        CP16(base + 8192 + so0, gBp);
        CP16(base + 8192 + so1, gBp + 16);
        CP_COMMIT();
    }

    for (int c = 0; c < NC; c++) {
        if (c + 1 < NC) {
            uint32_t bb = ((c + 1) & 1) ? 16384u : 0u;
            long ko = (long)(c + 1) * (BK * 2);
            CP16(base + bb + so0,        gAp + ko);
            CP16(base + bb + so1,        gAp + ko + 16);
            CP16(base + bb + 8192 + so0, gBp + ko);
            CP16(base + bb + 8192 + so1, gBp + ko + 16);
            CP_COMMIT();
            asm volatile("cp.async.wait_group 1;" ::: "memory");
        } else {
            asm volatile("cp.async.wait_group 0;" ::: "memory");
        }
        __syncthreads();

        uint32_t sA = base + ((c & 1) ? 16384u : 0u);
        uint32_t sB = sA + 8192u;

#pragma unroll
        for (int kk = 0; kk < 2; kk++) {
            int cA = kk*2 + cAoff;
            int cB = kk*2 + cBoff;
            uint32_t a[4][4], b[4][2];
#pragma unroll
            for (int mt = 0; mt < 4; mt++) {
                int r = rA[mt];
                uint32_t ad = sA + (uint32_t)((r*4 + (cA ^ ((r>>1)&3))) * 16);
                LDSM_X4(a[mt][0], a[mt][1], a[mt][2], a[mt][3], ad);
            }
#pragma unroll
            for (int nt = 0; nt < 4; nt++) {
                int r = rB[nt];
                uint32_t bd = sB + (uint32_t)((r*4 + (cB ^ ((r>>1)&3))) * 16);
                LDSM_X2(b[nt][0], b[nt][1], bd);
            }
#pragma unroll
            for (int mt = 0; mt < 4; mt++)
#pragma unroll
                for (int nt = 0; nt < 4; nt++)
                    MMA16816(acc[mt][nt], a[mt][0], a[mt][1], a[mt][2], a[mt][3],
                             b[nt][0], b[nt][1]);
        }
        __syncthreads();
    }

    // ---- epilogue
#pragma unroll
    for (int mt = 0; mt < 4; mt++) {
        int r0 = m0 + warp_m*64 + mt*16 + (lane >> 2);
        int r1 = r0 + 8;
        size_t o0 = (size_t)r0 * ldc;
        size_t o1 = (size_t)r1 * ldc;
#pragma unroll
        for (int nt = 0; nt < 4; nt++) {
            int col = n0 + warp_n*32 + nt*8 + (lane & 3)*2;
            if (col >= N) continue;
            float v0 = acc[mt][nt][0], v1 = acc[mt][nt][1];
            float v2 = acc[mt][nt][2], v3 = acc[mt][nt][3];
            if (bias)  { float b0 = bias[col], b1 = bias[col+1];
                         v0 += b0; v1 += b1; v2 += b0; v3 += b1; }
            if (resid) { const float2 q0 = *(const float2*)(resid + o0 + col);
                         const float2 q1 = *(const float2*)(resid + o1 + col);
                         v0 += q0.x; v1 += q0.y; v2 += q1.x; v3 += q1.y; }
            *(float2*)(C + o0 + col) = make_float2(v0, v1);
            *(float2*)(C + o1 + col) = make_float2(v2, v3);
        }
    }
}

// ================= split conversions =================
// A split: dst row = [hi(0..Kpad) | lo | hi], zero-padded where k >= K
__global__ void convA_k(const float* __restrict__ src, int K, int Kpad, long ldd,
                        __nv_bfloat16* __restrict__ dst)
{
    long idx = (long)blockIdx.x * blockDim.x + threadIdx.x;
    long tot = (long)BQ * Kpad;
    if (idx >= tot) return;
    int m = (int)(idx / Kpad), k = (int)(idx % Kpad);
    float v = (k < K) ? src[(long)m * K + k] : 0.f;
    __nv_bfloat16 hi = __float2bfloat16(v);
    __nv_bfloat16 lo = __float2bfloat16(v - __bfloat162float(hi));
    __nv_bfloat16* row = dst + (long)m * ldd;
    row[k] = hi; row[Kpad + k] = lo; row[2*Kpad + k] = hi;
}

// W[K,N] -> Bt[Npad, 3*Kpad]: row n = [hi | hi | lo], transposed, zero-padded
__global__ void convW_k(const float* __restrict__ W, int K, int N, int Kpad, int Npad,
                        long ldd, __nv_bfloat16* __restrict__ dst)
{
    __shared__ float t[32][33];
    int k0 = blockIdx.x * 32, nn0 = blockIdx.y * 32;
    int tx = threadIdx.x, ty = threadIdx.y;   // (32, 8)
#pragma unroll
    for (int i = ty; i < 32; i += 8) {
        int k = k0 + i, n = nn0 + tx;
        t[i][tx] = (k < K && n < N) ? W[(long)k * N + n] : 0.f;
    }
    __syncthreads();
#pragma unroll
    for (int i = ty; i < 32; i += 8) {
        int n = nn0 + i;
        if (n >= Npad) continue;
        int k = k0 + tx;
        float v = t[tx][i];
        __nv_bfloat16 hi = __float2bfloat16(v);
        __nv_bfloat16 lo = __float2bfloat16(v - __bfloat162float(hi));
        __nv_bfloat16* row = dst + (long)n * ldd;
        row[k] = hi; row[Kpad + k] = hi; row[2*Kpad + k] = lo;
    }
}

// ================= LayerNorm (eps = 2048) =================
__global__ void ln_kernel(const float* __restrict__ seq,
                          const float* __restrict__ sc,
                          const float* __restrict__ bi)
{
    int b = blockIdx.x, t = threadIdx.x;
    const float* row = seq + ((size_t)b << 11);
    float v[8]; float s = 0.f, sq = 0.f;
#pragma unroll
    for (int q = 0; q < 8; q++) { v[q] = row[q*256 + t]; s += v[q]; sq = fmaf(v[q], v[q], sq); }
    __shared__ float sh_s[8], sh_q[8];
    __shared__ float s_mu, s_inv;
#pragma unroll
    for (int o = 16; o; o >>= 1) {
        s  += __shfl_down_sync(0xffffffffu, s,  o);
        sq += __shfl_down_sync(0xffffffffu, sq, o);
    }
    int warp = t >> 5, lane = t & 31;
    if (lane == 0) { sh_s[warp] = s; sh_q[warp] = sq; }
    __syncthreads();
    if (t == 0) {
        float ts = 0.f, tq = 0.f;
        for (int w = 0; w < 8; w++) { ts += sh_s[w]; tq += sh_q[w]; }
        float mu = ts / 2048.f;
        float var = tq / 2048.f - mu*mu;
        s_mu = mu; s_inv = rsqrtf(var + 2048.0f);
    }
    __syncthreads();
    float mu = s_mu, inv = s_inv;
#pragma unroll
    for (int q = 0; q < 8; q++) {
        int col = q*256 + t;
        g_xt[((size_t)b << 11) + col] = (v[q] - mu) * inv * sc[col] + bi[col];
    }
}

// ================= gating + block-diag recurrence =================
__global__ void gate_kernel(
    const float* __restrict__ b_i, const float* __restrict__ b_f,
    const float* __restrict__ b_z, const float* __restrict__ b_o,
    const float* __restrict__ Riw, const float* __restrict__ Rib,
    const float* __restrict__ Rfw, const float* __restrict__ Rfb,
    const float* __restrict__ Rzw, const float* __restrict__ Rzb,
    const float* __restrict__ Row_, const float* __restrict__ Rob,
    const float* __restrict__ c_tm1, const float* __restrict__ n_tm1,
    const float* __restrict__ h_tm1, const float* __restrict__ m_tm1,
    float* __restrict__ out, int write_states)
{
    size_t idx = (size_t)blockIdx.x * blockDim.x + threadIdx.x;
    if (idx >= (size_t)N_ELE) return;
    int b = (int)(idx >> 11);
    int j = (int)(idx & 2047);
    int h = j >> 7;
    int rem = j & 127;
    int n = rem >> 3;
    int e = rem & 7;

    const float* hp = h_tm1 + ((size_t)b << 11) + (h << 7) + (n << 3);
    float hv[8];
#pragma unroll
    for (int d = 0; d < 8; d++) hv[d] = hp[d];
    int sb = n*8 + e;
    int wb = n*64 + e;
    float bi_ = Rib[sb], bf_ = Rfb[sb], bz_ = Rzb[sb], bo_ = Rob[sb];
#pragma unroll
    for (int d = 0; d < 8; d++) {
        float hd = hv[d];
        bi_ = fmaf(hd, Riw[wb + d*8], bi_);
        bf_ = fmaf(hd, Rfw[wb + d*8], bf_);
        bz_ = fmaf(hd, Rzw[wb + d*8], bz_);
        bo_ = fmaf(hd, Row_[wb + d*8], bo_);
    }

    float it = g_gates[idx]                    + b_i[j] + bi_;
    float ft = g_gates[(size_t)N_ELE   + idx]  + b_f[j] + bf_;
    float zt = g_gates[(size_t)2*N_ELE + idx]  + b_z[j] + bz_;
    float ot = g_gates[(size_t)3*N_ELE + idx]  + b_o[j] + bo_;

    float mprev = m_tm1[idx];
    float mt = fmaxf(ft + mprev, it);
    float ie = expf(it - mt);
    float fe = expf(ft - mt + mprev);
    float z  = tanhf(zt);
    float ct = fe * c_tm1[idx] + ie * z;
    float nt = fe * n_tm1[idx] + ie;
    float o  = 1.f / (1.f + expf(-ot));
    float ht = o * (ct / nt);

    g_ht[idx] = ht;
    if (write_states) {
        out[(size_t)N_ELE   + idx] = ct;
        out[(size_t)2*N_ELE + idx] = nt;
        out[(size_t)3*N_ELE + idx] = ht;
        out[(size_t)4*N_ELE + idx] = mt;
    }
}

// ================= GroupNorm =================
__global__ void gn_kernel(const float* __restrict__ sc, const float* __restrict__ bi)
{
    int b = blockIdx.x, t = threadIdx.x;
    __shared__ float row[2048];
    __shared__ float ps[256], pq[256];
    __shared__ float gmu[16], gis[16];
    const float* hr = g_ht + ((size_t)b << 11);
#pragma unroll
    for (int q = 0; q < 8; q++) row[q*256 + t] = hr[q*256 + t];
    __syncthreads();

    int g = t >> 4, p = t & 15;
    float s = 0.f, sq = 0.f;
#pragma unroll
    for (int dg = 0; dg < 8; dg++) {
        float v = row[p*128 + g*8 + dg];
        s += v; sq = fmaf(v, v, sq);
    }
    ps[t] = s; pq[t] = sq;
    __syncthreads();
    for (int st = 8; st > 0; st >>= 1) {
        if (p < st) { ps[t] += ps[t + st]; pq[t] += pq[t + st]; }
        __syncthreads();
    }
    if (p == 0) {
        float mu = ps[t] / 128.f;
        float var = pq[t] / 128.f - mu*mu;
        gmu[g] = mu; gis[g] = rsqrtf(var + 1e-6f);
    }
    __syncthreads();
#pragma unroll
    for (int q = 0; q < 8; q++) {
        int col = q*256 + t;
        int hd = col & 127;
        int gg = hd >> 3;
        float v = (row[col] - gmu[gg]) * gis[gg];
        g_xt[((size_t)b << 11) + col] = v * sc[hd] + bi[hd];
    }
}

// ================= GLU =================
__global__ void glu_kernel()
{
    long idx = (long)blockIdx.x * blockDim.x + threadIdx.x;
    long tot = (long)BQ * PROJ;
    if (idx >= tot) return;
    int b = (int)(idx / PROJ);
    int j = (int)(idx % PROJ);
    const float* up = g_gates + (long)b * UPN;
    float a = up[j];
    float x = up[j + PROJ];
    float x3 = x * x * x;
    float gg = 0.5f * x * (1.f + tanhf(0.7978845608028654f * (x + 0.044715f * x3)));
    g_gated[idx] = a + gg;
}

// ================= driver =================
extern "C" void kernel_launch(void* const* d_in, const int* in_sizes, int n_in,
                              void* d_out, int out_size)
{
    const float* seq      = (const float*)d_in[0];
    const float* c_tm1    = (const float*)d_in[1];
    const float* n_tm1    = (const float*)d_in[2];
    const float* h_tm1    = (const float*)d_in[3];
    const float* m_tm1    = (const float*)d_in[4];
    const float* ln_scale = (const float*)d_in[5];
    const float* ln_bias  = (const float*)d_in[6];
    const float* W_z      = (const float*)d_in[7];
    const float* b_z      = (const float*)d_in[8];
    const float* W_i      = (const float*)d_in[9];
    const float* b_i      = (const float*)d_in[10];
    const float* W_f      = (const float*)d_in[11];
    const float* b_f      = (const float*)d_in[12];
    const float* W_o      = (const float*)d_in[13];
    const float* b_o      = (const float*)d_in[14];
    const float* R_z_w    = (const float*)d_in[15];
    const float* R_z_b    = (const float*)d_in[16];
    const float* R_i_w    = (const float*)d_in[17];
    const float* R_i_b    = (const float*)d_in[18];
    const float* R_f_w    = (const float*)d_in[19];
    const float* R_f_b    = (const float*)d_in[20];
    const float* R_o_w    = (const float*)d_in[21];
    const float* R_o_b    = (const float*)d_in[22];
    const float* gn_scale = (const float*)d_in[23];
    const float* gn_bias  = (const float*)d_in[24];
    const float* up_w     = (const float*)d_in[25];
    const float* up_b     = (const float*)d_in[26];
    const float* down_w   = (const float*)d_in[27];
    const float* down_b   = (const float*)d_in[28];
    float* out = (float*)d_out;

    int write_states = (out_size >= 5 * N_ELE) ? 1 : 0;

    void *pA, *pBg, *pBu, *pBd, *pXT, *pG, *pGated;
    cudaGetSymbolAddress(&pA,  gA);
    cudaGetSymbolAddress(&pBg, gBg);
    cudaGetSymbolAddress(&pBu, gBu);
    cudaGetSymbolAddress(&pBd, gBd);
    cudaGetSymbolAddress(&pXT, g_xt);
    cudaGetSymbolAddress(&pG,  g_gates);
    cudaGetSymbolAddress(&pGated, g_gated);
    __nv_bfloat16* A  = (__nv_bfloat16*)pA;
    __nv_bfloat16* Bg = (__nv_bfloat16*)pBg;
    __nv_bfloat16* Bu = (__nv_bfloat16*)pBu;
    __nv_bfloat16* Bd = (__nv_bfloat16*)pBd;
    float* xt    = (float*)pXT;
    float* gates = (float*)pG;
    float* gated = (float*)pGated;

    dim3 cw(32, 8);

    // weight conversions (order-independent w.r.t. the activation chain)
    convW_k<<<dim3(KP1/32, DD/32), cw>>>(W_i, DD, DD, KP1, DD, LDA1, Bg + 0L*DD*LDA1);
    convW_k<<<dim3(KP1/32, DD/32), cw>>>(W_f, DD, DD, KP1, DD, LDA1, Bg + 1L*DD*LDA1);
    convW_k<<<dim3(KP1/32, DD/32), cw>>>(W_z, DD, DD, KP1, DD, LDA1, Bg + 2L*DD*LDA1);
    convW_k<<<dim3(KP1/32, DD/32), cw>>>(W_o, DD, DD, KP1, DD, LDA1, Bg + 3L*DD*LDA1);
    convW_k<<<dim3(KP1/32, NPAD_UP/32), cw>>>(up_w,   DD,   UPN, KP1, NPAD_UP, LDA1, Bu);
    convW_k<<<dim3(KP2/32, DD/32), cw>>>(down_w, PROJ, DD,  KP2, DD,      LDA2, Bd);

    // 1. LayerNorm
    ln_kernel<<<BQ, 256>>>(seq, ln_scale, ln_bias);

    // 2. split x_t
    convA_k<<<(unsigned)(((long)BQ*KP1 + 255)/256), 256>>>(xt, DD, KP1, LDA1, A);

    // 3. four gate GEMMs (batched over z): slabs [i,f,z,o]
    mma_gemm<<<dim3(DD/BN, BQ/BM, 4), 256>>>(
        A, LDA1, Bg, LDA1, gates, DD, DD, LDA1,
        (long)DD*LDA1, (long)N_ELE, nullptr, nullptr);

    // 4. gating + recurrence + states
    gate_kernel<<<N_ELE/256, 256>>>(b_i, b_f, b_z, b_o,
                                    R_i_w, R_i_b, R_f_w, R_f_b,
                                    R_z_w, R_z_b, R_o_w, R_o_b,
                                    c_tm1, n_tm1, h_tm1, m_tm1,
                                    out, write_states);

    // 5. GroupNorm -> g_xt
    gn_kernel<<<BQ, 256>>>(gn_scale, gn_bias);

    // 6. split GN output, up GEMM (+bias)
    convA_k<<<(unsigned)(((long)BQ*KP1 + 255)/256), 256>>>(xt, DD, KP1, LDA1, A);
    mma_gemm<<<dim3((UPN + BN - 1)/BN, BQ/BM, 1), 256>>>(
        A, LDA1, Bu, LDA1, gates, UPN, UPN, LDA1, 0, 0, up_b, nullptr);

    // 7. GLU
    glu_kernel<<<(unsigned)(((long)BQ*PROJ + 255)/256), 256>>>();

    // 8. split gated, down GEMM (+bias +residual)
    convA_k<<<(unsigned)(((long)BQ*KP2 + 255)/256), 256>>>(gated, PROJ, KP2, LDA2, A);
    mma_gemm<<<dim3(DD/BN, BQ/BM, 1), 256>>>(
        A, LDA2, Bd, LDA2, out, DD, DD, LDA2, 0, 0, down_b, seq);
}